// round 12
// baseline (speedup 1.0000x reference)
#include <cuda_runtime.h>
#include <cuda_bf16.h>
#include <cstdint>

// Problem constants
#define BB 4
#define SS 2048
#define DD 1024
#define HH 16
#define HDD 64
#define MM (BB*SS)        // 8192
#define NQKV (3*DD)       // 3072

// ---------------------------------------------------------------------------
// Scratch (device globals; no runtime allocation allowed)
// ---------------------------------------------------------------------------
// Q/K/V bf16 hi/lo in [B,H,S,HD] (Q pre-scaled by 0.125)
__device__ __nv_bfloat16 g_qhi[(size_t)BB*HH*SS*HDD];
__device__ __nv_bfloat16 g_qlo[(size_t)BB*HH*SS*HDD];
__device__ __nv_bfloat16 g_khi[(size_t)BB*HH*SS*HDD];
__device__ __nv_bfloat16 g_klo[(size_t)BB*HH*SS*HDD];
__device__ __nv_bfloat16 g_vhi[(size_t)BB*HH*SS*HDD];
__device__ __nv_bfloat16 g_vlo[(size_t)BB*HH*SS*HDD];
// bf16 split operands for GEMMs
__device__ __nv_bfloat16 g_xhi[(size_t)MM*DD];
__device__ __nv_bfloat16 g_xlo[(size_t)MM*DD];
__device__ __nv_bfloat16 g_ahi[(size_t)MM*DD];
__device__ __nv_bfloat16 g_alo[(size_t)MM*DD];
__device__ __nv_bfloat16 g_wqhi[(size_t)NQKV*DD];   // W_qkv^T [3072,1024]
__device__ __nv_bfloat16 g_wqlo[(size_t)NQKV*DD];
__device__ __nv_bfloat16 g_wohi[(size_t)DD*DD];     // W_out^T [1024,1024]
__device__ __nv_bfloat16 g_wolo[(size_t)DD*DD];

// ---------------------------------------------------------------------------
// PTX helpers (sm_80-compatible only: ldmatrix / mma.sync / cp.async)
// ---------------------------------------------------------------------------
__device__ __forceinline__ uint32_t smem_u32(const void* p) {
    uint32_t a;
    asm("{ .reg .u64 t; cvta.to.shared.u64 t, %1; cvt.u32.u64 %0, t; }" : "=r"(a) : "l"(p));
    return a;
}

#define LDSM_X4(r0, r1, r2, r3, addr) \
    asm volatile("ldmatrix.sync.aligned.m8n8.x4.shared.b16 {%0,%1,%2,%3}, [%4];" \
        : "=r"(r0), "=r"(r1), "=r"(r2), "=r"(r3) : "r"(addr))

#define LDSM_X4_T(r0, r1, r2, r3, addr) \
    asm volatile("ldmatrix.sync.aligned.m8n8.x4.trans.shared.b16 {%0,%1,%2,%3}, [%4];" \
        : "=r"(r0), "=r"(r1), "=r"(r2), "=r"(r3) : "r"(addr))

#define MMA16816(c, a, b0, b1) \
    asm volatile("mma.sync.aligned.m16n8k16.row.col.f32.bf16.bf16.f32 " \
        "{%0,%1,%2,%3}, {%4,%5,%6,%7}, {%8,%9}, {%0,%1,%2,%3};" \
        : "+f"((c)[0]), "+f"((c)[1]), "+f"((c)[2]), "+f"((c)[3]) \
        : "r"((a)[0]), "r"((a)[1]), "r"((a)[2]), "r"((a)[3]), "r"(b0), "r"(b1))

#define CP_ASYNC16(dst, src) \
    asm volatile("cp.async.cg.shared.global [%0], [%1], 16;" :: "r"(dst), "l"(src))
#define CP_COMMIT() asm volatile("cp.async.commit_group;" ::: "memory")
#define CP_WAIT1()  asm volatile("cp.async.wait_group 1;" ::: "memory")
#define CP_WAIT0()  asm volatile("cp.async.wait_group 0;" ::: "memory")

__device__ __forceinline__ uint32_t pack_bf16(float a, float b) {
    __nv_bfloat162 t;
    t.x = __float2bfloat16(a);
    t.y = __float2bfloat16(b);
    return *(uint32_t*)&t;
}

// ---------------------------------------------------------------------------
// Conversion pre-passes
// ---------------------------------------------------------------------------
__global__ void split_x_kernel(const float* __restrict__ in) {
    int i4 = (blockIdx.x * blockDim.x + threadIdx.x) * 4;
    float4 v = *(const float4*)(in + i4);
    float vv[4] = {v.x, v.y, v.z, v.w};
#pragma unroll
    for (int j = 0; j < 4; ++j) {
        __nv_bfloat16 h = __float2bfloat16(vv[j]);
        g_xhi[i4 + j] = h;
        g_xlo[i4 + j] = __float2bfloat16(vv[j] - __bfloat162float(h));
    }
}

// in [K,N] fp32 -> out [N,K] bf16 hi/lo.  sel 0 -> W_qkv, sel 1 -> W_out
__global__ void transpose_split_kernel(const float* __restrict__ in, int K, int N, int sel) {
    __shared__ float t[32][33];
    const int n0 = blockIdx.x * 32, k0 = blockIdx.y * 32;
    const int x = threadIdx.x, y = threadIdx.y;
#pragma unroll
    for (int dy = 0; dy < 32; dy += 8)
        t[y + dy][x] = in[(size_t)(k0 + y + dy) * N + n0 + x];
    __syncthreads();
    __nv_bfloat16* hi = sel ? g_wohi : g_wqhi;
    __nv_bfloat16* lo = sel ? g_wolo : g_wqlo;
#pragma unroll
    for (int dy = 0; dy < 32; dy += 8) {
        float v = t[x][y + dy];
        size_t o = (size_t)(n0 + y + dy) * K + k0 + x;
        __nv_bfloat16 h = __float2bfloat16(v);
        hi[o] = h;
        lo[o] = __float2bfloat16(v - __bfloat162float(h));
    }
}

// ---------------------------------------------------------------------------
// HMMA GEMM: C[M,N] = A[M,K] * B^T + bias  (bf16 3-term split, fp32 accum)
// 128x128 CTA tile, BK=32, 256 threads, 8 warps (4m x 2n), warp tile 32x64.
// 3-stage cp.async pipeline (3 x 32KB), ONE __syncthreads per K-chunk.
// __launch_bounds__(256,2): 2 CTAs/SM (192KB smem + 128 regs fit).
// MODE 0: A=g_x*, B=g_wq*; epilogue writes Q/K/V bf16 hi/lo (Q scaled 0.125)
// MODE 1: A=g_a*, B=g_wo*; epilogue writes Cout fp32
// ---------------------------------------------------------------------------
#define HG_STAGE 32768
#define HG_SMEM (3 * HG_STAGE)   // 98304

template<int MODE>
__device__ __forceinline__ void hg_load_stage(
    uint32_t smbase, int st, int kk, int m0, int n0, int tid,
    const __nv_bfloat16* __restrict__ Ahi, const __nv_bfloat16* __restrict__ Alo,
    const __nv_bfloat16* __restrict__ Bhi, const __nv_bfloat16* __restrict__ Blo)
{
    const uint32_t sb = smbase + (uint32_t)st * HG_STAGE;
#pragma unroll
    for (int i = 0; i < 8; ++i) {
        const __nv_bfloat16* base = (i < 2) ? Ahi : (i < 4) ? Alo : (i < 6) ? Bhi : Blo;
        const int r0 = (i < 4) ? m0 : n0;
        const int w = ((i & 1) << 8) + tid;         // 0..511
        const int row = w >> 2;                     // 0..127
        const int c = w & 3;                        // 16B chunk in row
        const __nv_bfloat16* src = base + (size_t)(r0 + row) * DD + kk + c * 8;
        const uint32_t dst = sb + (uint32_t)(i >> 1) * 8192
                           + (uint32_t)(row * 64) + (uint32_t)((c ^ ((row >> 1) & 3)) << 4);
        CP_ASYNC16(dst, src);
    }
}

template<int MODE>
__global__ __launch_bounds__(256, 2) void hmma_gemm(
    const float* __restrict__ bias, float* __restrict__ Cout)
{
    extern __shared__ __align__(1024) char sm[];
    const uint32_t smbase = smem_u32(sm);

    const int tid = threadIdx.x;
    const int wid = tid >> 5, lane = tid & 31;
    const int wm = wid & 3, wn = wid >> 2;
    const int n0 = blockIdx.x * 128;
    const int m0 = blockIdx.y * 128;

    const __nv_bfloat16 *Ahi, *Alo, *Bhi, *Blo;
    if (MODE == 0) { Ahi = g_xhi; Alo = g_xlo; Bhi = g_wqhi; Blo = g_wqlo; }
    else           { Ahi = g_ahi; Alo = g_alo; Bhi = g_wohi; Blo = g_wolo; }

    float acc[2][8][4];
#pragma unroll
    for (int mi = 0; mi < 2; ++mi)
#pragma unroll
        for (int ni = 0; ni < 8; ++ni)
#pragma unroll
            for (int j = 0; j < 4; ++j) acc[mi][ni][j] = 0.f;

    // prologue: stages 0 and 1 in flight
    hg_load_stage<MODE>(smbase, 0, 0,  m0, n0, tid, Ahi, Alo, Bhi, Blo);
    CP_COMMIT();
    hg_load_stage<MODE>(smbase, 1, 32, m0, n0, tid, Ahi, Alo, Bhi, Blo);
    CP_COMMIT();

    const int NCH = DD / 32;     // 32
    int st = 0;                  // c % 3
    int stn = 2;                 // (c+2) % 3
    for (int c = 0; c < NCH; ++c) {
        CP_WAIT1();              // stage c resident (pending = stage c+1 only)
        __syncthreads();         // all warps done reading buffer stn (iter c-1) + see stage c

        if (c + 2 < NCH)
            hg_load_stage<MODE>(smbase, stn, (c + 2) * 32, m0, n0, tid,
                                Ahi, Alo, Bhi, Blo);
        CP_COMMIT();             // always commit (empty group near tail keeps counts aligned)

        const uint32_t sa = smbase + (uint32_t)st * HG_STAGE;
#pragma unroll
        for (int k16 = 0; k16 < 2; ++k16) {
            uint32_t ah[2][4], al[2][4];
            const int arow = wm * 32 + (lane & 15);
            const int chA = k16 * 2 + (lane >> 4);
#pragma unroll
            for (int mi = 0; mi < 2; ++mi) {
                const int r = arow + mi * 16;
                const uint32_t off = (uint32_t)(r * 64) + (uint32_t)((chA ^ ((r >> 1) & 3)) << 4);
                LDSM_X4(ah[mi][0], ah[mi][1], ah[mi][2], ah[mi][3], sa + off);
                LDSM_X4(al[mi][0], al[mi][1], al[mi][2], al[mi][3], sa + 8192 + off);
            }
            const int brow = wn * 64 + ((lane >> 4) << 3) + (lane & 7);
            const int chB = k16 * 2 + ((lane >> 3) & 1);
#pragma unroll
            for (int bp = 0; bp < 4; ++bp) {
                const int r = brow + bp * 16;
                const uint32_t off = (uint32_t)(r * 64) + (uint32_t)((chB ^ ((r >> 1) & 3)) << 4);
                uint32_t bh[4], bl[4];
                LDSM_X4(bh[0], bh[1], bh[2], bh[3], sa + 16384 + off);
                LDSM_X4(bl[0], bl[1], bl[2], bl[3], sa + 24576 + off);
#pragma unroll
                for (int mi = 0; mi < 2; ++mi) {
                    MMA16816(acc[mi][2 * bp],     ah[mi], bh[0], bh[1]);
                    MMA16816(acc[mi][2 * bp],     ah[mi], bl[0], bl[1]);
                    MMA16816(acc[mi][2 * bp],     al[mi], bh[0], bh[1]);
                    MMA16816(acc[mi][2 * bp + 1], ah[mi], bh[2], bh[3]);
                    MMA16816(acc[mi][2 * bp + 1], ah[mi], bl[2], bl[3]);
                    MMA16816(acc[mi][2 * bp + 1], al[mi], bh[2], bh[3]);
                }
            }
        }
        st = (st == 2) ? 0 : st + 1;
        stn = (stn == 2) ? 0 : stn + 1;
    }

    // Epilogue
#pragma unroll
    for (int mi = 0; mi < 2; ++mi) {
#pragma unroll
        for (int ni = 0; ni < 8; ++ni) {
            const int row = m0 + wm * 32 + mi * 16 + (lane >> 2);
            const int col = n0 + wn * 64 + ni * 8 + ((lane & 3) << 1);
            const float b0 = bias[col], b1 = bias[col + 1];
#pragma unroll
            for (int half = 0; half < 2; ++half) {
                const int r = row + half * 8;
                float v0 = acc[mi][ni][half * 2] + b0;
                float v1 = acc[mi][ni][half * 2 + 1] + b1;
                if (MODE == 0) {
                    const int sect = col >> 10, dd = col & 1023;
                    const int h = dd >> 6, hd = dd & 63;
                    const int b_ = r >> 11, s_ = r & 2047;
                    if (sect == 0) { v0 *= 0.125f; v1 *= 0.125f; }
                    const size_t idx = ((((size_t)b_ * HH) + h) * SS + s_) * HDD + hd;
                    __nv_bfloat162 hi2, lo2;
                    hi2.x = __float2bfloat16(v0);
                    hi2.y = __float2bfloat16(v1);
                    lo2.x = __float2bfloat16(v0 - __bfloat162float(hi2.x));
                    lo2.y = __float2bfloat16(v1 - __bfloat162float(hi2.y));
                    __nv_bfloat16* dh = (sect == 0) ? g_qhi : (sect == 1) ? g_khi : g_vhi;
                    __nv_bfloat16* dl = (sect == 0) ? g_qlo : (sect == 1) ? g_klo : g_vlo;
                    *(__nv_bfloat162*)&dh[idx] = hi2;
                    *(__nv_bfloat162*)&dl[idx] = lo2;
                } else {
                    *(float2*)&Cout[(size_t)r * DD + col] = make_float2(v0, v1);
                }
            }
        }
    }
}

// ---------------------------------------------------------------------------
// HMMA causal flash attention. BQ=64, BK=64, 128 threads (4 warps x m16).
// Q frags register-resident; K/V hi/lo double-buffered cp.async stages.
// Stage layout (32KB): Khi[8K] Klo[8K] Vhi[8K] Vlo[8K]; row=64 bf16=128B,
// 8x16B chunks, swizzle chunk' = c ^ (row & 7).
// Longest-work CTAs (largest qt) launch first for tail balance.
// ---------------------------------------------------------------------------
#define AT_SMEM 65536

__device__ __forceinline__ void at_load_kv(uint32_t smbase, int st, int k0,
    const __nv_bfloat16* __restrict__ Kh, const __nv_bfloat16* __restrict__ Kl,
    const __nv_bfloat16* __restrict__ Vh, const __nv_bfloat16* __restrict__ Vl,
    int tid)
{
    const uint32_t sb = smbase + (uint32_t)st * 32768;
#pragma unroll
    for (int i = 0; i < 16; ++i) {
        const int idx = tid + i * 128;       // 0..2047
        const int tile = idx >> 9;           // 0:Khi 1:Klo 2:Vhi 3:Vlo
        const int w = idx & 511;
        const int row = w >> 3, c = w & 7;
        const __nv_bfloat16* base = (tile == 0) ? Kh : (tile == 1) ? Kl
                                  : (tile == 2) ? Vh : Vl;
        const __nv_bfloat16* src = base + (size_t)(k0 + row) * HDD + c * 8;
        const uint32_t dst = sb + (uint32_t)tile * 8192u + (uint32_t)(row * 128)
                           + ((uint32_t)(c ^ (row & 7)) << 4);
        CP_ASYNC16(dst, src);
    }
}

__global__ __launch_bounds__(128) void attn_hmma()
{
    extern __shared__ __align__(1024) char sm[];
    const uint32_t smbase = smem_u32(sm);

    const int qt = gridDim.x - 1 - blockIdx.x;   // longest first
    const int bh = blockIdx.y;
    const int tid = threadIdx.x;
    const int warp = tid >> 5, lane = tid & 31;
    const int q0 = qt * 64;

    const size_t boff = (size_t)bh * SS * HDD;
    const __nv_bfloat16* Qh = g_qhi + boff;
    const __nv_bfloat16* Ql = g_qlo + boff;
    const __nv_bfloat16* Kh = g_khi + boff;
    const __nv_bfloat16* Kl = g_klo + boff;
    const __nv_bfloat16* Vh = g_vhi + boff;
    const __nv_bfloat16* Vl = g_vlo + boff;

    // ---- stage Q hi/lo into smem (stage-0 area), then load fragments ----
#pragma unroll
    for (int i = 0; i < 8; ++i) {
        const int idx = tid + i * 128;       // 0..1023
        const int tile = idx >> 9;           // 0:hi 1:lo
        const int w = idx & 511;
        const int row = w >> 3, c = w & 7;
        const __nv_bfloat16* src = (tile ? Ql : Qh) + (size_t)(q0 + row) * HDD + c * 8;
        const uint32_t dst = smbase + (uint32_t)tile * 8192u + (uint32_t)(row * 128)
                           + ((uint32_t)(c ^ (row & 7)) << 4);
        CP_ASYNC16(dst, src);
    }
    CP_COMMIT();
    CP_WAIT0();
    __syncthreads();

    uint32_t qh[4][4], ql[4][4];
    {
        const int arow = warp * 16 + (lane & 15);
#pragma unroll
        for (int ks = 0; ks < 4; ++ks) {
            const int ch = ks * 2 + (lane >> 4);
            const uint32_t off = (uint32_t)(arow * 128) + ((uint32_t)(ch ^ (arow & 7)) << 4);
            LDSM_X4(qh[ks][0], qh[ks][1], qh[ks][2], qh[ks][3], smbase + off);
            LDSM_X4(ql[ks][0], ql[ks][1], ql[ks][2], ql[ks][3], smbase + 8192 + off);
        }
    }
    __syncthreads();    // Q smem free for KV stage 0

    float ao[8][4];
#pragma unroll
    for (int ni = 0; ni < 8; ++ni)
#pragma unroll
        for (int j = 0; j < 4; ++j) ao[ni][j] = 0.f;
    float m0 = -1e30f, m1 = -1e30f, l0 = 0.f, l1 = 0.f;

    at_load_kv(smbase, 0, 0, Kh, Kl, Vh, Vl, tid);
    CP_COMMIT();

    for (int kt = 0; kt <= qt; ++kt) {
        if (kt < qt) {
            at_load_kv(smbase, (kt + 1) & 1, (kt + 1) * 64, Kh, Kl, Vh, Vl, tid);
            CP_COMMIT();
            CP_WAIT1();
        } else {
            CP_WAIT0();
        }
        __syncthreads();

        const uint32_t sv = smbase + (uint32_t)(kt & 1) * 32768;

        // ---- scores: S = Qhi*Khi + Qhi*Klo + Qlo*Khi ----
        float as[8][4];
#pragma unroll
        for (int ni = 0; ni < 8; ++ni)
#pragma unroll
            for (int j = 0; j < 4; ++j) as[ni][j] = 0.f;

#pragma unroll
        for (int ks = 0; ks < 4; ++ks) {
#pragma unroll
            for (int np = 0; np < 4; ++np) {
                const int brow = np * 16 + ((lane >> 4) << 3) + (lane & 7);
                const int ch = ks * 2 + ((lane >> 3) & 1);
                const uint32_t off = (uint32_t)(brow * 128) + ((uint32_t)(ch ^ (brow & 7)) << 4);
                uint32_t kh[4], kl[4];
                LDSM_X4(kh[0], kh[1], kh[2], kh[3], sv + off);
                LDSM_X4(kl[0], kl[1], kl[2], kl[3], sv + 8192 + off);
                MMA16816(as[2 * np],     qh[ks], kh[0], kh[1]);
                MMA16816(as[2 * np],     qh[ks], kl[0], kl[1]);
                MMA16816(as[2 * np],     ql[ks], kh[0], kh[1]);
                MMA16816(as[2 * np + 1], qh[ks], kh[2], kh[3]);
                MMA16816(as[2 * np + 1], qh[ks], kl[2], kl[3]);
                MMA16816(as[2 * np + 1], ql[ks], kh[2], kh[3]);
            }
        }

        // ---- causal mask (diagonal tile only) ----
        if (kt == qt) {
            const int r0 = q0 + warp * 16 + (lane >> 2);
            const int c0 = kt * 64 + ((lane & 3) << 1);
#pragma unroll
            for (int ni = 0; ni < 8; ++ni) {
                const int cc = c0 + ni * 8;
                if (cc     > r0)     as[ni][0] = -1e30f;
                if (cc + 1 > r0)     as[ni][1] = -1e30f;
                if (cc     > r0 + 8) as[ni][2] = -1e30f;
                if (cc + 1 > r0 + 8) as[ni][3] = -1e30f;
            }
        }

        // ---- online softmax (rows r0 = lane>>2, r1 = r0+8) ----
        float tm0 = -1e30f, tm1 = -1e30f;
#pragma unroll
        for (int ni = 0; ni < 8; ++ni) {
            tm0 = fmaxf(tm0, fmaxf(as[ni][0], as[ni][1]));
            tm1 = fmaxf(tm1, fmaxf(as[ni][2], as[ni][3]));
        }
#pragma unroll
        for (int off = 1; off <= 2; off <<= 1) {
            tm0 = fmaxf(tm0, __shfl_xor_sync(0xffffffffu, tm0, off));
            tm1 = fmaxf(tm1, __shfl_xor_sync(0xffffffffu, tm1, off));
        }
        const float nm0 = fmaxf(m0, tm0), nm1 = fmaxf(m1, tm1);
        const float cr0 = __expf(m0 - nm0), cr1 = __expf(m1 - nm1);
        m0 = nm0; m1 = nm1;
        float rs0 = 0.f, rs1 = 0.f;
#pragma unroll
        for (int ni = 0; ni < 8; ++ni) {
            as[ni][0] = __expf(as[ni][0] - nm0); rs0 += as[ni][0];
            as[ni][1] = __expf(as[ni][1] - nm0); rs0 += as[ni][1];
            as[ni][2] = __expf(as[ni][2] - nm1); rs1 += as[ni][2];
            as[ni][3] = __expf(as[ni][3] - nm1); rs1 += as[ni][3];
        }
#pragma unroll
        for (int off = 1; off <= 2; off <<= 1) {
            rs0 += __shfl_xor_sync(0xffffffffu, rs0, off);
            rs1 += __shfl_xor_sync(0xffffffffu, rs1, off);
        }
        l0 = l0 * cr0 + rs0;
        l1 = l1 * cr1 + rs1;
#pragma unroll
        for (int ni = 0; ni < 8; ++ni) {
            ao[ni][0] *= cr0; ao[ni][1] *= cr0;
            ao[ni][2] *= cr1; ao[ni][3] *= cr1;
        }

        // ---- O += Phi*Vhi + Phi*Vlo + Plo*Vhi ----
#pragma unroll
        for (int ks = 0; ks < 4; ++ks) {
            uint32_t phi[4], plo[4];
            {
                const float p00 = as[2 * ks][0],     p01 = as[2 * ks][1];
                const float p02 = as[2 * ks][2],     p03 = as[2 * ks][3];
                const float p10 = as[2 * ks + 1][0], p11 = as[2 * ks + 1][1];
                const float p12 = as[2 * ks + 1][2], p13 = as[2 * ks + 1][3];
                phi[0] = pack_bf16(p00, p01);
                phi[1] = pack_bf16(p02, p03);
                phi[2] = pack_bf16(p10, p11);
                phi[3] = pack_bf16(p12, p13);
                const __nv_bfloat162* h0 = (const __nv_bfloat162*)&phi[0];
                const __nv_bfloat162* h1 = (const __nv_bfloat162*)&phi[1];
                const __nv_bfloat162* h2 = (const __nv_bfloat162*)&phi[2];
                const __nv_bfloat162* h3 = (const __nv_bfloat162*)&phi[3];
                plo[0] = pack_bf16(p00 - __bfloat162float(h0->x), p01 - __bfloat162float(h0->y));
                plo[1] = pack_bf16(p02 - __bfloat162float(h1->x), p03 - __bfloat162float(h1->y));
                plo[2] = pack_bf16(p10 - __bfloat162float(h2->x), p11 - __bfloat162float(h2->y));
                plo[3] = pack_bf16(p12 - __bfloat162float(h3->x), p13 - __bfloat162float(h3->y));
            }
#pragma unroll
            for (int np = 0; np < 4; ++np) {
                const int vrow = ks * 16 + ((lane >> 4) << 3) + (lane & 7);
                const int ch = np * 2 + ((lane >> 3) & 1);
                const uint32_t off = (uint32_t)(vrow * 128) + ((uint32_t)(ch ^ (vrow & 7)) << 4);
                uint32_t vh[4], vl[4];
                LDSM_X4_T(vh[0], vh[1], vh[2], vh[3], sv + 16384 + off);
                LDSM_X4_T(vl[0], vl[1], vl[2], vl[3], sv + 24576 + off);
                MMA16816(ao[2 * np],     phi, vh[0], vh[2]);
                MMA16816(ao[2 * np],     phi, vl[0], vl[2]);
                MMA16816(ao[2 * np],     plo, vh[0], vh[2]);
                MMA16816(ao[2 * np + 1], phi, vh[1], vh[3]);
                MMA16816(ao[2 * np + 1], phi, vl[1], vl[3]);
                MMA16816(ao[2 * np + 1], plo, vh[1], vh[3]);
            }
        }
        __syncthreads();   // all reads done before next stage overwrites
    }

    // ---- epilogue: O/l -> g_ahi/g_alo ([B,S,D], col = h*64 + hd) ----
    const float inv0 = 1.f / l0, inv1 = 1.f / l1;
    const int b_ = bh >> 4, h_ = bh & 15;
    const int r0 = q0 + warp * 16 + (lane >> 2);
    const int c0 = (lane & 3) << 1;
#pragma unroll
    for (int ni = 0; ni < 8; ++ni) {
        const int hd = ni * 8 + c0;
#pragma unroll
        for (int half = 0; half < 2; ++half) {
            const int r = r0 + half * 8;
            const float inv = half ? inv1 : inv0;
            const float v0 = ao[ni][half * 2] * inv;
            const float v1 = ao[ni][half * 2 + 1] * inv;
            const size_t idx = ((size_t)(b_ * SS + r)) * DD + h_ * HDD + hd;
            __nv_bfloat162 hi2, lo2;
            hi2.x = __float2bfloat16(v0);
            hi2.y = __float2bfloat16(v1);
            lo2.x = __float2bfloat16(v0 - __bfloat162float(hi2.x));
            lo2.y = __float2bfloat16(v1 - __bfloat162float(hi2.y));
            *(__nv_bfloat162*)&g_ahi[idx] = hi2;
            *(__nv_bfloat162*)&g_alo[idx] = lo2;
        }
    }
}

// ---------------------------------------------------------------------------
extern "C" void kernel_launch(void* const* d_in, const int* in_sizes, int n_in,
                              void* d_out, int out_size)
{
    const float* x     = (const float*)d_in[0];
    const float* W_qkv = (const float*)d_in[1];
    const float* b_qkv = (const float*)d_in[2];
    const float* W_out = (const float*)d_in[3];
    const float* b_out = (const float*)d_in[4];
    float* out = (float*)d_out;

    cudaFuncSetAttribute(hmma_gemm<0>, cudaFuncAttributeMaxDynamicSharedMemorySize, HG_SMEM);
    cudaFuncSetAttribute(hmma_gemm<1>, cudaFuncAttributeMaxDynamicSharedMemorySize, HG_SMEM);
    cudaFuncSetAttribute(attn_hmma, cudaFuncAttributeMaxDynamicSharedMemorySize, AT_SMEM);

    // 0) operand conversion / transpose pre-passes
    split_x_kernel<<<(MM * DD) / 1024, 256>>>(x);
    transpose_split_kernel<<<dim3(NQKV / 32, DD / 32), dim3(32, 8)>>>(W_qkv, DD, NQKV, 0);
    transpose_split_kernel<<<dim3(DD / 32, DD / 32), dim3(32, 8)>>>(W_out, DD, DD, 1);

    // 1) QKV projection (HMMA) -> Q/K/V bf16 hi/lo
    hmma_gemm<0><<<dim3(NQKV / 128, MM / 128), 256, HG_SMEM>>>(b_qkv, nullptr);

    // 2) Causal attention (HMMA) -> g_ahi/g_alo
    attn_hmma<<<dim3(SS / 64, BB * HH), 128, AT_SMEM>>>();

    // 3) Output projection (HMMA) -> d_out
    hmma_gemm<1><<<dim3(DD / 128, MM / 128), 256, HG_SMEM>>>(b_out, out);
}

// round 13
// speedup vs baseline: 1.0143x; 1.0143x over previous
#include <cuda_runtime.h>
#include <cuda_bf16.h>
#include <cstdint>

// Problem constants
#define BB 4
#define SS 2048
#define DD 1024
#define HH 16
#define HDD 64
#define MM (BB*SS)        // 8192
#define NQKV (3*DD)       // 3072

// ---------------------------------------------------------------------------
// Scratch (device globals; no runtime allocation allowed)
// ---------------------------------------------------------------------------
// Q/K/V bf16 hi/lo in [B,H,S,HD] (Q pre-scaled by 0.125*log2(e))
__device__ __nv_bfloat16 g_qhi[(size_t)BB*HH*SS*HDD];
__device__ __nv_bfloat16 g_qlo[(size_t)BB*HH*SS*HDD];
__device__ __nv_bfloat16 g_khi[(size_t)BB*HH*SS*HDD];
__device__ __nv_bfloat16 g_klo[(size_t)BB*HH*SS*HDD];
__device__ __nv_bfloat16 g_vhi[(size_t)BB*HH*SS*HDD];
__device__ __nv_bfloat16 g_vlo[(size_t)BB*HH*SS*HDD];
// bf16 split operands for GEMMs
__device__ __nv_bfloat16 g_xhi[(size_t)MM*DD];
__device__ __nv_bfloat16 g_xlo[(size_t)MM*DD];
__device__ __nv_bfloat16 g_ahi[(size_t)MM*DD];
__device__ __nv_bfloat16 g_alo[(size_t)MM*DD];
__device__ __nv_bfloat16 g_wqhi[(size_t)NQKV*DD];   // W_qkv^T [3072,1024]
__device__ __nv_bfloat16 g_wqlo[(size_t)NQKV*DD];
__device__ __nv_bfloat16 g_wohi[(size_t)DD*DD];     // W_out^T [1024,1024]
__device__ __nv_bfloat16 g_wolo[(size_t)DD*DD];

// ---------------------------------------------------------------------------
// PTX helpers (sm_80-compatible only: ldmatrix / mma.sync / cp.async)
// ---------------------------------------------------------------------------
__device__ __forceinline__ uint32_t smem_u32(const void* p) {
    uint32_t a;
    asm("{ .reg .u64 t; cvta.to.shared.u64 t, %1; cvt.u32.u64 %0, t; }" : "=r"(a) : "l"(p));
    return a;
}

#define LDSM_X4(r0, r1, r2, r3, addr) \
    asm volatile("ldmatrix.sync.aligned.m8n8.x4.shared.b16 {%0,%1,%2,%3}, [%4];" \
        : "=r"(r0), "=r"(r1), "=r"(r2), "=r"(r3) : "r"(addr))

#define LDSM_X4_T(r0, r1, r2, r3, addr) \
    asm volatile("ldmatrix.sync.aligned.m8n8.x4.trans.shared.b16 {%0,%1,%2,%3}, [%4];" \
        : "=r"(r0), "=r"(r1), "=r"(r2), "=r"(r3) : "r"(addr))

// NOTE: no volatile — register-only op; lets ptxas schedule/interleave MMAs.
#define MMA16816(c, a, b0, b1) \
    asm("mma.sync.aligned.m16n8k16.row.col.f32.bf16.bf16.f32 " \
        "{%0,%1,%2,%3}, {%4,%5,%6,%7}, {%8,%9}, {%0,%1,%2,%3};" \
        : "+f"((c)[0]), "+f"((c)[1]), "+f"((c)[2]), "+f"((c)[3]) \
        : "r"((a)[0]), "r"((a)[1]), "r"((a)[2]), "r"((a)[3]), "r"(b0), "r"(b1))

#define CP_ASYNC16(dst, src) \
    asm volatile("cp.async.cg.shared.global [%0], [%1], 16;" :: "r"(dst), "l"(src))
#define CP_COMMIT() asm volatile("cp.async.commit_group;" ::: "memory")
#define CP_WAIT1()  asm volatile("cp.async.wait_group 1;" ::: "memory")
#define CP_WAIT0()  asm volatile("cp.async.wait_group 0;" ::: "memory")

__device__ __forceinline__ uint32_t pack_bf16(float a, float b) {
    __nv_bfloat162 t;
    t.x = __float2bfloat16(a);
    t.y = __float2bfloat16(b);
    return *(uint32_t*)&t;
}

// ---------------------------------------------------------------------------
// Conversion pre-passes
// ---------------------------------------------------------------------------
__global__ void split_x_kernel(const float* __restrict__ in) {
    int i4 = (blockIdx.x * blockDim.x + threadIdx.x) * 4;
    float4 v = *(const float4*)(in + i4);
    float vv[4] = {v.x, v.y, v.z, v.w};
#pragma unroll
    for (int j = 0; j < 4; ++j) {
        __nv_bfloat16 h = __float2bfloat16(vv[j]);
        g_xhi[i4 + j] = h;
        g_xlo[i4 + j] = __float2bfloat16(vv[j] - __bfloat162float(h));
    }
}

// in [K,N] fp32 -> out [N,K] bf16 hi/lo.  sel 0 -> W_qkv, sel 1 -> W_out
__global__ void transpose_split_kernel(const float* __restrict__ in, int K, int N, int sel) {
    __shared__ float t[32][33];
    const int n0 = blockIdx.x * 32, k0 = blockIdx.y * 32;
    const int x = threadIdx.x, y = threadIdx.y;
#pragma unroll
    for (int dy = 0; dy < 32; dy += 8)
        t[y + dy][x] = in[(size_t)(k0 + y + dy) * N + n0 + x];
    __syncthreads();
    __nv_bfloat16* hi = sel ? g_wohi : g_wqhi;
    __nv_bfloat16* lo = sel ? g_wolo : g_wqlo;
#pragma unroll
    for (int dy = 0; dy < 32; dy += 8) {
        float v = t[x][y + dy];
        size_t o = (size_t)(n0 + y + dy) * K + k0 + x;
        __nv_bfloat16 h = __float2bfloat16(v);
        hi[o] = h;
        lo[o] = __float2bfloat16(v - __bfloat162float(h));
    }
}

// ---------------------------------------------------------------------------
// HMMA GEMM: C[M,N] = A[M,K] * B^T + bias  (bf16 3-term split, fp32 accum)
// 128x128 CTA tile, BK=32, 256 threads, 8 warps (4m x 2n), warp tile 32x64.
// 3-stage cp.async pipeline, one __syncthreads per K-chunk, 2 CTAs/SM.
// MMAs ordered term-major: adjacent MMAs hit different accumulators.
// MODE 0: epilogue writes Q/K/V bf16 hi/lo (Q scaled 0.125*log2e)
// MODE 1: epilogue writes Cout fp32
// ---------------------------------------------------------------------------
#define HG_STAGE 32768
#define HG_SMEM (3 * HG_STAGE)   // 98304

template<int MODE>
__device__ __forceinline__ void hg_load_stage(
    uint32_t smbase, int st, int kk, int m0, int n0, int tid,
    const __nv_bfloat16* __restrict__ Ahi, const __nv_bfloat16* __restrict__ Alo,
    const __nv_bfloat16* __restrict__ Bhi, const __nv_bfloat16* __restrict__ Blo)
{
    const uint32_t sb = smbase + (uint32_t)st * HG_STAGE;
#pragma unroll
    for (int i = 0; i < 8; ++i) {
        const __nv_bfloat16* base = (i < 2) ? Ahi : (i < 4) ? Alo : (i < 6) ? Bhi : Blo;
        const int r0 = (i < 4) ? m0 : n0;
        const int w = ((i & 1) << 8) + tid;         // 0..511
        const int row = w >> 2;                     // 0..127
        const int c = w & 3;                        // 16B chunk in row
        const __nv_bfloat16* src = base + (size_t)(r0 + row) * DD + kk + c * 8;
        const uint32_t dst = sb + (uint32_t)(i >> 1) * 8192
                           + (uint32_t)(row * 64) + (uint32_t)((c ^ ((row >> 1) & 3)) << 4);
        CP_ASYNC16(dst, src);
    }
}

template<int MODE>
__global__ __launch_bounds__(256, 2) void hmma_gemm(
    const float* __restrict__ bias, float* __restrict__ Cout)
{
    extern __shared__ __align__(1024) char sm[];
    const uint32_t smbase = smem_u32(sm);

    const int tid = threadIdx.x;
    const int wid = tid >> 5, lane = tid & 31;
    const int wm = wid & 3, wn = wid >> 2;
    const int n0 = blockIdx.x * 128;
    const int m0 = blockIdx.y * 128;

    const __nv_bfloat16 *Ahi, *Alo, *Bhi, *Blo;
    if (MODE == 0) { Ahi = g_xhi; Alo = g_xlo; Bhi = g_wqhi; Blo = g_wqlo; }
    else           { Ahi = g_ahi; Alo = g_alo; Bhi = g_wohi; Blo = g_wolo; }

    float acc[2][8][4];
#pragma unroll
    for (int mi = 0; mi < 2; ++mi)
#pragma unroll
        for (int ni = 0; ni < 8; ++ni)
#pragma unroll
            for (int j = 0; j < 4; ++j) acc[mi][ni][j] = 0.f;

    // prologue: stages 0 and 1 in flight
    hg_load_stage<MODE>(smbase, 0, 0,  m0, n0, tid, Ahi, Alo, Bhi, Blo);
    CP_COMMIT();
    hg_load_stage<MODE>(smbase, 1, 32, m0, n0, tid, Ahi, Alo, Bhi, Blo);
    CP_COMMIT();

    const int NCH = DD / 32;     // 32
    int st = 0;                  // c % 3
    int stn = 2;                 // (c+2) % 3
    for (int c = 0; c < NCH; ++c) {
        CP_WAIT1();              // stage c resident
        __syncthreads();

        if (c + 2 < NCH)
            hg_load_stage<MODE>(smbase, stn, (c + 2) * 32, m0, n0, tid,
                                Ahi, Alo, Bhi, Blo);
        CP_COMMIT();

        const uint32_t sa = smbase + (uint32_t)st * HG_STAGE;
#pragma unroll
        for (int k16 = 0; k16 < 2; ++k16) {
            uint32_t ah[2][4], al[2][4];
            const int arow = wm * 32 + (lane & 15);
            const int chA = k16 * 2 + (lane >> 4);
#pragma unroll
            for (int mi = 0; mi < 2; ++mi) {
                const int r = arow + mi * 16;
                const uint32_t off = (uint32_t)(r * 64) + (uint32_t)((chA ^ ((r >> 1) & 3)) << 4);
                LDSM_X4(ah[mi][0], ah[mi][1], ah[mi][2], ah[mi][3], sa + off);
                LDSM_X4(al[mi][0], al[mi][1], al[mi][2], al[mi][3], sa + 8192 + off);
            }
            const int brow = wn * 64 + ((lane >> 4) << 3) + (lane & 7);
            const int chB = k16 * 2 + ((lane >> 3) & 1);
#pragma unroll
            for (int bp = 0; bp < 4; ++bp) {
                const int r = brow + bp * 16;
                const uint32_t off = (uint32_t)(r * 64) + (uint32_t)((chB ^ ((r >> 1) & 3)) << 4);
                uint32_t bh[4], bl[4];
                LDSM_X4(bh[0], bh[1], bh[2], bh[3], sa + 16384 + off);
                LDSM_X4(bl[0], bl[1], bl[2], bl[3], sa + 24576 + off);
                // term-major: adjacent MMAs target distinct accumulators
                MMA16816(acc[0][2 * bp],     ah[0], bh[0], bh[1]);
                MMA16816(acc[1][2 * bp],     ah[1], bh[0], bh[1]);
                MMA16816(acc[0][2 * bp + 1], ah[0], bh[2], bh[3]);
                MMA16816(acc[1][2 * bp + 1], ah[1], bh[2], bh[3]);
                MMA16816(acc[0][2 * bp],     ah[0], bl[0], bl[1]);
                MMA16816(acc[1][2 * bp],     ah[1], bl[0], bl[1]);
                MMA16816(acc[0][2 * bp + 1], ah[0], bl[2], bl[3]);
                MMA16816(acc[1][2 * bp + 1], ah[1], bl[2], bl[3]);
                MMA16816(acc[0][2 * bp],     al[0], bh[0], bh[1]);
                MMA16816(acc[1][2 * bp],     al[1], bh[0], bh[1]);
                MMA16816(acc[0][2 * bp + 1], al[0], bh[2], bh[3]);
                MMA16816(acc[1][2 * bp + 1], al[1], bh[2], bh[3]);
            }
        }
        st = (st == 2) ? 0 : st + 1;
        stn = (stn == 2) ? 0 : stn + 1;
    }

    // Epilogue
#pragma unroll
    for (int mi = 0; mi < 2; ++mi) {
#pragma unroll
        for (int ni = 0; ni < 8; ++ni) {
            const int row = m0 + wm * 32 + mi * 16 + (lane >> 2);
            const int col = n0 + wn * 64 + ni * 8 + ((lane & 3) << 1);
            const float b0 = bias[col], b1 = bias[col + 1];
#pragma unroll
            for (int half = 0; half < 2; ++half) {
                const int r = row + half * 8;
                float v0 = acc[mi][ni][half * 2] + b0;
                float v1 = acc[mi][ni][half * 2 + 1] + b1;
                if (MODE == 0) {
                    const int sect = col >> 10, dd = col & 1023;
                    const int h = dd >> 6, hd = dd & 63;
                    const int b_ = r >> 11, s_ = r & 2047;
                    if (sect == 0) {
                        // 1/sqrt(64) * log2(e): base-2 softmax downstream
                        const float QS = 0.125f * 1.4426950408889634f;
                        v0 *= QS; v1 *= QS;
                    }
                    const size_t idx = ((((size_t)b_ * HH) + h) * SS + s_) * HDD + hd;
                    __nv_bfloat162 hi2, lo2;
                    hi2.x = __float2bfloat16(v0);
                    hi2.y = __float2bfloat16(v1);
                    lo2.x = __float2bfloat16(v0 - __bfloat162float(hi2.x));
                    lo2.y = __float2bfloat16(v1 - __bfloat162float(hi2.y));
                    __nv_bfloat16* dh = (sect == 0) ? g_qhi : (sect == 1) ? g_khi : g_vhi;
                    __nv_bfloat16* dl = (sect == 0) ? g_qlo : (sect == 1) ? g_klo : g_vlo;
                    *(__nv_bfloat162*)&dh[idx] = hi2;
                    *(__nv_bfloat162*)&dl[idx] = lo2;
                } else {
                    *(float2*)&Cout[(size_t)r * DD + col] = make_float2(v0, v1);
                }
            }
        }
    }
}

// ---------------------------------------------------------------------------
// HMMA causal flash attention. BQ=64, BK=64, 128 threads (4 warps x m16).
// Base-2 online softmax (Q pre-scaled by 0.125*log2e; exp2f -> MUFU.EX2).
// MMAs ordered so adjacent MMAs target distinct accumulators.
// ---------------------------------------------------------------------------
#define AT_SMEM 65536

__device__ __forceinline__ void at_load_kv(uint32_t smbase, int st, int k0,
    const __nv_bfloat16* __restrict__ Kh, const __nv_bfloat16* __restrict__ Kl,
    const __nv_bfloat16* __restrict__ Vh, const __nv_bfloat16* __restrict__ Vl,
    int tid)
{
    const uint32_t sb = smbase + (uint32_t)st * 32768;
#pragma unroll
    for (int i = 0; i < 16; ++i) {
        const int idx = tid + i * 128;       // 0..2047
        const int tile = idx >> 9;           // 0:Khi 1:Klo 2:Vhi 3:Vlo
        const int w = idx & 511;
        const int row = w >> 3, c = w & 7;
        const __nv_bfloat16* base = (tile == 0) ? Kh : (tile == 1) ? Kl
                                  : (tile == 2) ? Vh : Vl;
        const __nv_bfloat16* src = base + (size_t)(k0 + row) * HDD + c * 8;
        const uint32_t dst = sb + (uint32_t)tile * 8192u + (uint32_t)(row * 128)
                           + ((uint32_t)(c ^ (row & 7)) << 4);
        CP_ASYNC16(dst, src);
    }
}

__global__ __launch_bounds__(128) void attn_hmma()
{
    extern __shared__ __align__(1024) char sm[];
    const uint32_t smbase = smem_u32(sm);

    const int qt = gridDim.x - 1 - blockIdx.x;   // longest first
    const int bh = blockIdx.y;
    const int tid = threadIdx.x;
    const int warp = tid >> 5, lane = tid & 31;
    const int q0 = qt * 64;

    const size_t boff = (size_t)bh * SS * HDD;
    const __nv_bfloat16* Qh = g_qhi + boff;
    const __nv_bfloat16* Ql = g_qlo + boff;
    const __nv_bfloat16* Kh = g_khi + boff;
    const __nv_bfloat16* Kl = g_klo + boff;
    const __nv_bfloat16* Vh = g_vhi + boff;
    const __nv_bfloat16* Vl = g_vlo + boff;

    // ---- stage Q hi/lo into smem (stage-0 area), then load fragments ----
#pragma unroll
    for (int i = 0; i < 8; ++i) {
        const int idx = tid + i * 128;       // 0..1023
        const int tile = idx >> 9;           // 0:hi 1:lo
        const int w = idx & 511;
        const int row = w >> 3, c = w & 7;
        const __nv_bfloat16* src = (tile ? Ql : Qh) + (size_t)(q0 + row) * HDD + c * 8;
        const uint32_t dst = smbase + (uint32_t)tile * 8192u + (uint32_t)(row * 128)
                           + ((uint32_t)(c ^ (row & 7)) << 4);
        CP_ASYNC16(dst, src);
    }
    CP_COMMIT();
    CP_WAIT0();
    __syncthreads();

    uint32_t qh[4][4], ql[4][4];
    {
        const int arow = warp * 16 + (lane & 15);
#pragma unroll
        for (int ks = 0; ks < 4; ++ks) {
            const int ch = ks * 2 + (lane >> 4);
            const uint32_t off = (uint32_t)(arow * 128) + ((uint32_t)(ch ^ (arow & 7)) << 4);
            LDSM_X4(qh[ks][0], qh[ks][1], qh[ks][2], qh[ks][3], smbase + off);
            LDSM_X4(ql[ks][0], ql[ks][1], ql[ks][2], ql[ks][3], smbase + 8192 + off);
        }
    }
    __syncthreads();    // Q smem free for KV stage 0

    float ao[8][4];
#pragma unroll
    for (int ni = 0; ni < 8; ++ni)
#pragma unroll
        for (int j = 0; j < 4; ++j) ao[ni][j] = 0.f;
    float m0 = -1e30f, m1 = -1e30f, l0 = 0.f, l1 = 0.f;

    at_load_kv(smbase, 0, 0, Kh, Kl, Vh, Vl, tid);
    CP_COMMIT();

    for (int kt = 0; kt <= qt; ++kt) {
        if (kt < qt) {
            at_load_kv(smbase, (kt + 1) & 1, (kt + 1) * 64, Kh, Kl, Vh, Vl, tid);
            CP_COMMIT();
            CP_WAIT1();
        } else {
            CP_WAIT0();
        }
        __syncthreads();

        const uint32_t sv = smbase + (uint32_t)(kt & 1) * 32768;

        // ---- scores: S = Qhi*Khi + Qhi*Klo + Qlo*Khi  (base-2 scaled) ----
        float as[8][4];
#pragma unroll
        for (int ni = 0; ni < 8; ++ni)
#pragma unroll
            for (int j = 0; j < 4; ++j) as[ni][j] = 0.f;

#pragma unroll
        for (int ks = 0; ks < 4; ++ks) {
#pragma unroll
            for (int np = 0; np < 4; ++np) {
                const int brow = np * 16 + ((lane >> 4) << 3) + (lane & 7);
                const int ch = ks * 2 + ((lane >> 3) & 1);
                const uint32_t off = (uint32_t)(brow * 128) + ((uint32_t)(ch ^ (brow & 7)) << 4);
                uint32_t kh[4], kl[4];
                LDSM_X4(kh[0], kh[1], kh[2], kh[3], sv + off);
                LDSM_X4(kl[0], kl[1], kl[2], kl[3], sv + 8192 + off);
                // interleave terms across the two accumulators
                MMA16816(as[2 * np],     qh[ks], kh[0], kh[1]);
                MMA16816(as[2 * np + 1], qh[ks], kh[2], kh[3]);
                MMA16816(as[2 * np],     qh[ks], kl[0], kl[1]);
                MMA16816(as[2 * np + 1], qh[ks], kl[2], kl[3]);
                MMA16816(as[2 * np],     ql[ks], kh[0], kh[1]);
                MMA16816(as[2 * np + 1], ql[ks], kh[2], kh[3]);
            }
        }

        // ---- causal mask (diagonal tile only) ----
        if (kt == qt) {
            const int r0 = q0 + warp * 16 + (lane >> 2);
            const int c0 = kt * 64 + ((lane & 3) << 1);
#pragma unroll
            for (int ni = 0; ni < 8; ++ni) {
                const int cc = c0 + ni * 8;
                if (cc     > r0)     as[ni][0] = -1e30f;
                if (cc + 1 > r0)     as[ni][1] = -1e30f;
                if (cc     > r0 + 8) as[ni][2] = -1e30f;
                if (cc + 1 > r0 + 8) as[ni][3] = -1e30f;
            }
        }

        // ---- base-2 online softmax (rows r0 = lane>>2, r1 = r0+8) ----
        float tm0 = -1e30f, tm1 = -1e30f;
#pragma unroll
        for (int ni = 0; ni < 8; ++ni) {
            tm0 = fmaxf(tm0, fmaxf(as[ni][0], as[ni][1]));
            tm1 = fmaxf(tm1, fmaxf(as[ni][2], as[ni][3]));
        }
#pragma unroll
        for (int off = 1; off <= 2; off <<= 1) {
            tm0 = fmaxf(tm0, __shfl_xor_sync(0xffffffffu, tm0, off));
            tm1 = fmaxf(tm1, __shfl_xor_sync(0xffffffffu, tm1, off));
        }
        const float nm0 = fmaxf(m0, tm0), nm1 = fmaxf(m1, tm1);
        const float cr0 = exp2f(m0 - nm0), cr1 = exp2f(m1 - nm1);
        m0 = nm0; m1 = nm1;
        float rs0 = 0.f, rs1 = 0.f;
#pragma unroll
        for (int ni = 0; ni < 8; ++ni) {
            as[ni][0] = exp2f(as[ni][0] - nm0); rs0 += as[ni][0];
            as[ni][1] = exp2f(as[ni][1] - nm0); rs0 += as[ni][1];
            as[ni][2] = exp2f(as[ni][2] - nm1); rs1 += as[ni][2];
            as[ni][3] = exp2f(as[ni][3] - nm1); rs1 += as[ni][3];
        }
#pragma unroll
        for (int off = 1; off <= 2; off <<= 1) {
            rs0 += __shfl_xor_sync(0xffffffffu, rs0, off);
            rs1 += __shfl_xor_sync(0xffffffffu, rs1, off);
        }
        l0 = l0 * cr0 + rs0;
        l1 = l1 * cr1 + rs1;
#pragma unroll
        for (int ni = 0; ni < 8; ++ni) {
            ao[ni][0] *= cr0; ao[ni][1] *= cr0;
            ao[ni][2] *= cr1; ao[ni][3] *= cr1;
        }

        // ---- O += Phi*Vhi + Phi*Vlo + Plo*Vhi ----
#pragma unroll
        for (int ks = 0; ks < 4; ++ks) {
            uint32_t phi[4], plo[4];
            {
                const float p00 = as[2 * ks][0],     p01 = as[2 * ks][1];
                const float p02 = as[2 * ks][2],     p03 = as[2 * ks][3];
                const float p10 = as[2 * ks + 1][0], p11 = as[2 * ks + 1][1];
                const float p12 = as[2 * ks + 1][2], p13 = as[2 * ks + 1][3];
                phi[0] = pack_bf16(p00, p01);
                phi[1] = pack_bf16(p02, p03);
                phi[2] = pack_bf16(p10, p11);
                phi[3] = pack_bf16(p12, p13);
                const __nv_bfloat162* h0 = (const __nv_bfloat162*)&phi[0];
                const __nv_bfloat162* h1 = (const __nv_bfloat162*)&phi[1];
                const __nv_bfloat162* h2 = (const __nv_bfloat162*)&phi[2];
                const __nv_bfloat162* h3 = (const __nv_bfloat162*)&phi[3];
                plo[0] = pack_bf16(p00 - __bfloat162float(h0->x), p01 - __bfloat162float(h0->y));
                plo[1] = pack_bf16(p02 - __bfloat162float(h1->x), p03 - __bfloat162float(h1->y));
                plo[2] = pack_bf16(p10 - __bfloat162float(h2->x), p11 - __bfloat162float(h2->y));
                plo[3] = pack_bf16(p12 - __bfloat162float(h3->x), p13 - __bfloat162float(h3->y));
            }
#pragma unroll
            for (int np = 0; np < 4; ++np) {
                const int vrow = ks * 16 + ((lane >> 4) << 3) + (lane & 7);
                const int ch = np * 2 + ((lane >> 3) & 1);
                const uint32_t off = (uint32_t)(vrow * 128) + ((uint32_t)(ch ^ (vrow & 7)) << 4);
                uint32_t vh[4], vl[4];
                LDSM_X4_T(vh[0], vh[1], vh[2], vh[3], sv + 16384 + off);
                LDSM_X4_T(vl[0], vl[1], vl[2], vl[3], sv + 24576 + off);
                // interleave terms across the two accumulators
                MMA16816(ao[2 * np],     phi, vh[0], vh[2]);
                MMA16816(ao[2 * np + 1], phi, vh[1], vh[3]);
                MMA16816(ao[2 * np],     phi, vl[0], vl[2]);
                MMA16816(ao[2 * np + 1], phi, vl[1], vl[3]);
                MMA16816(ao[2 * np],     plo, vh[0], vh[2]);
                MMA16816(ao[2 * np + 1], plo, vh[1], vh[3]);
            }
        }
        __syncthreads();   // all reads done before next stage overwrites
    }

    // ---- epilogue: O/l -> g_ahi/g_alo ([B,S,D], col = h*64 + hd) ----
    const float inv0 = 1.f / l0, inv1 = 1.f / l1;
    const int b_ = bh >> 4, h_ = bh & 15;
    const int r0 = q0 + warp * 16 + (lane >> 2);
    const int c0 = (lane & 3) << 1;
#pragma unroll
    for (int ni = 0; ni < 8; ++ni) {
        const int hd = ni * 8 + c0;
#pragma unroll
        for (int half = 0; half < 2; ++half) {
            const int r = r0 + half * 8;
            const float inv = half ? inv1 : inv0;
            const float v0 = ao[ni][half * 2] * inv;
            const float v1 = ao[ni][half * 2 + 1] * inv;
            const size_t idx = ((size_t)(b_ * SS + r)) * DD + h_ * HDD + hd;
            __nv_bfloat162 hi2, lo2;
            hi2.x = __float2bfloat16(v0);
            hi2.y = __float2bfloat16(v1);
            lo2.x = __float2bfloat16(v0 - __bfloat162float(hi2.x));
            lo2.y = __float2bfloat16(v1 - __bfloat162float(hi2.y));
            *(__nv_bfloat162*)&g_ahi[idx] = hi2;
            *(__nv_bfloat162*)&g_alo[idx] = lo2;
        }
    }
}

// ---------------------------------------------------------------------------
extern "C" void kernel_launch(void* const* d_in, const int* in_sizes, int n_in,
                              void* d_out, int out_size)
{
    const float* x     = (const float*)d_in[0];
    const float* W_qkv = (const float*)d_in[1];
    const float* b_qkv = (const float*)d_in[2];
    const float* W_out = (const float*)d_in[3];
    const float* b_out = (const float*)d_in[4];
    float* out = (float*)d_out;

    cudaFuncSetAttribute(hmma_gemm<0>, cudaFuncAttributeMaxDynamicSharedMemorySize, HG_SMEM);
    cudaFuncSetAttribute(hmma_gemm<1>, cudaFuncAttributeMaxDynamicSharedMemorySize, HG_SMEM);
    cudaFuncSetAttribute(attn_hmma, cudaFuncAttributeMaxDynamicSharedMemorySize, AT_SMEM);

    // 0) operand conversion / transpose pre-passes
    split_x_kernel<<<(MM * DD) / 1024, 256>>>(x);
    transpose_split_kernel<<<dim3(NQKV / 32, DD / 32), dim3(32, 8)>>>(W_qkv, DD, NQKV, 0);
    transpose_split_kernel<<<dim3(DD / 32, DD / 32), dim3(32, 8)>>>(W_out, DD, DD, 1);

    // 1) QKV projection (HMMA) -> Q/K/V bf16 hi/lo
    hmma_gemm<0><<<dim3(NQKV / 128, MM / 128), 256, HG_SMEM>>>(b_qkv, nullptr);

    // 2) Causal attention (HMMA) -> g_ahi/g_alo
    attn_hmma<<<dim3(SS / 64, BB * HH), 128, AT_SMEM>>>();

    // 3) Output projection (HMMA) -> d_out
    hmma_gemm<1><<<dim3(DD / 128, MM / 128), 256, HG_SMEM>>>(b_out, out);
}